// round 16
// baseline (speedup 1.0000x reference)
#include <cuda_runtime.h>
#include <cuda_bf16.h>

// Output = C_total * conv3x3(inp, k): the 1000-step LIF recurrence is linear for
// I in [0,9) (spike/reset clamps provably inactive), so it collapses to a scalar.
//
// R15: champion R14 (256-thr blocks, 2-col threads, batch-2 rows, 32 regs, 1024
// blocks single wave, __stcs stores, uniform 16 pair-iterations — kernel
// 20.38us) + dependency-tiered FMAs: compute all A/B-operand terms BEFORE the
// first use of the in-flight C row, and all C terms before the first use of D,
// storing the s-pair before u completes. Same FMA count / loads / registers;
// purely biases the scheduler to cover the load latency with resident-operand
// math.

#define TW   256   // threads per block (each handles 2 output columns)
#define ROWS 32    // output rows per block

struct Row { float2 lo, hi; };   // input cols x0..x0+3 for this thread

__device__ __forceinline__ Row load_row(const float* p)
{
    Row r;
    r.lo = *(const float2*)p;               // default policy: halo rows hit L2
    r.hi = *(const float2*)(p + 2);
    return r;
}

__global__ __launch_bounds__(TW, 7)
void snn_conv_kernel(const float* __restrict__ inp,
                     const float* __restrict__ kw,
                     float* __restrict__ out,
                     float cscale)
{
    const int W  = 512;
    const int OW = 510;

    const int n  = blockIdx.y;
    int y0 = blockIdx.x * ROWS;              // 0,32,...,480
    if (y0 > 478) y0 = 478;                  // last strip overlaps by 2 rows:
                                             // all blocks run full 16 pair-iters
    const int t  = threadIdx.x;

    const bool valid = (2 * t) <= 508;       // thread 255 computes garbage, no store
    const int  x0    = valid ? 2 * t : 508;  // clamp keeps all loads in-bounds

    // 3x3 weights with the LIF scalar folded in
    const float k00 = kw[0]*cscale, k01 = kw[1]*cscale, k02 = kw[2]*cscale;
    const float k10 = kw[3]*cscale, k11 = kw[4]*cscale, k12 = kw[5]*cscale;
    const float k20 = kw[6]*cscale, k21 = kw[7]*cscale, k22 = kw[8]*cscale;

    const float* pin = inp + (size_t)n * W * W + (size_t)y0 * W + x0;
    float*       po  = out + (size_t)n * OW * OW + (size_t)y0 * OW + x0;

    // Window: A=row y, B=row y+1 (persistent); C,D loaded per pair-iteration.
    Row A = load_row(pin);
    Row B = load_row(pin + W);
    pin += 2 * W;                            // points at row y0+2

#pragma unroll
    for (int p = 0; p < ROWS / 2; p++) {
        // Issue BOTH row loads up front: 4 independent LDG.64 in flight
        Row C = load_row(pin);
        Row D = load_row(pin + W);
        pin += 2 * W;

        // ── Tier 1: A/B-only terms (operands resident) — covers C/D latency ──
        float s0 = k00*A.lo.x + k01*A.lo.y + k02*A.hi.x
                 + k10*B.lo.x + k11*B.lo.y + k12*B.hi.x;
        float s1 = k00*A.lo.y + k01*A.hi.x + k02*A.hi.y
                 + k10*B.lo.y + k11*B.hi.x + k12*B.hi.y;
        float u0 = k00*B.lo.x + k01*B.lo.y + k02*B.hi.x;
        float u1 = k00*B.lo.y + k01*B.hi.x + k02*B.hi.y;

        // ── Tier 2: C terms (first C use is ~13 FFMAs after load issue) ──
        s0 += k20*C.lo.x + k21*C.lo.y + k22*C.hi.x;
        s1 += k20*C.lo.y + k21*C.hi.x + k22*C.hi.y;
        u0 += k10*C.lo.x + k11*C.lo.y + k12*C.hi.x;
        u1 += k10*C.lo.y + k11*C.hi.x + k12*C.hi.y;

        if (valid)                           // s-pair is final: store before u math
            __stcs((float2*)(po), make_float2(s0, s1));

        // ── Tier 3: D terms ──
        u0 += k20*D.lo.x + k21*D.lo.y + k22*D.hi.x;
        u1 += k20*D.lo.y + k21*D.hi.x + k22*D.hi.y;

        if (valid)
            __stcs((float2*)(po + OW), make_float2(u0, u1));
        po += 2 * OW;

        A = C;
        B = D;
    }
}

extern "C" void kernel_launch(void* const* d_in, const int* in_sizes, int n_in,
                              void* d_out, int out_size)
{
    const float* inp = (const float*)d_in[0];   // (64,512,512,1) fp32
    const float* k   = (const float*)d_in[1];   // (3,3,1,1) fp32
    float* out = (float*)d_out;                 // (64,510,510,1) fp32

    // Closed-form LIF coefficient (double precision, host, once per capture).
    const double DT = 0.01, R = 3000.0, C = 10.0, NS = 1000.0;
    double v  = (R * 1.0) / (R * C) * DT;   // v0 = 1e-3
    double vt = v;
    for (int i = 0; i < 999; i++) {
        v  = v + (-v + R * 1.0) / (R * C) * DT;
        vt = (v + vt) / NS;
    }
    const float cscale = (float)vt;         // ~1.0008e-3

    dim3 block(TW);
    dim3 grid((510 + ROWS - 1) / ROWS, 64); // 16 x 64 = 1024 blocks, single wave
    snn_conv_kernel<<<grid, block>>>(inp, k, out, cscale);
}

// round 17
// speedup vs baseline: 1.0552x; 1.0552x over previous
#include <cuda_runtime.h>
#include <cuda_bf16.h>

// Output = C_total * conv3x3(inp, k): the 1000-step LIF recurrence is linear for
// I in [0,9) (spike/reset clamps provably inactive), so it collapses to a scalar.
//
// R16 = R14 verbatim (the measured optimum: kernel 20.38us, dur 24.58us).
// Config: 256-thr blocks, 2-col threads, batch-2 rows (4 independent LDG.64 per
// stall epoch), 32 regs, 1024 blocks = single wave, __stcs stores (output never
// re-read), uniform 16 pair-iterations via 2-row overlap of the last strip.
// R15 showed FMA tiering is neutral (ptxas already schedules it); batch-4 is
// reg-cost-prohibitive (~46 regs -> 62% occ, the proven-loser region). The
// kernel sits at ~98% of the compulsory-traffic wall; submitting the champion
// unchanged maximizes expected score.

#define TW   256   // threads per block (each handles 2 output columns)
#define ROWS 32    // output rows per block

struct Row { float2 lo, hi; };   // input cols x0..x0+3 for this thread

__device__ __forceinline__ Row load_row(const float* p)
{
    Row r;
    r.lo = *(const float2*)p;               // default policy: halo rows hit L2
    r.hi = *(const float2*)(p + 2);
    return r;
}

__global__ __launch_bounds__(TW, 7)
void snn_conv_kernel(const float* __restrict__ inp,
                     const float* __restrict__ kw,
                     float* __restrict__ out,
                     float cscale)
{
    const int W  = 512;
    const int OW = 510;

    const int n  = blockIdx.y;
    int y0 = blockIdx.x * ROWS;              // 0,32,...,480
    if (y0 > 478) y0 = 478;                  // last strip overlaps by 2 rows:
                                             // all blocks run full 16 pair-iters
    const int t  = threadIdx.x;

    const bool valid = (2 * t) <= 508;       // thread 255 computes garbage, no store
    const int  x0    = valid ? 2 * t : 508;  // clamp keeps all loads in-bounds

    // 3x3 weights with the LIF scalar folded in
    const float k00 = kw[0]*cscale, k01 = kw[1]*cscale, k02 = kw[2]*cscale;
    const float k10 = kw[3]*cscale, k11 = kw[4]*cscale, k12 = kw[5]*cscale;
    const float k20 = kw[6]*cscale, k21 = kw[7]*cscale, k22 = kw[8]*cscale;

    const float* pin = inp + (size_t)n * W * W + (size_t)y0 * W + x0;
    float*       po  = out + (size_t)n * OW * OW + (size_t)y0 * OW + x0;

    // Window: A=row y, B=row y+1 (persistent); C,D loaded per pair-iteration.
    Row A = load_row(pin);
    Row B = load_row(pin + W);
    pin += 2 * W;                            // points at row y0+2

#pragma unroll
    for (int p = 0; p < ROWS / 2; p++) {
        // Issue BOTH row loads up front: 4 independent LDG.64 in flight
        Row C = load_row(pin);
        Row D = load_row(pin + W);
        pin += 2 * W;

        // out(y): rows A,B,C   |   out(y+1): rows B,C,D
        float s0 = k00*A.lo.x + k01*A.lo.y + k02*A.hi.x
                 + k10*B.lo.x + k11*B.lo.y + k12*B.hi.x
                 + k20*C.lo.x + k21*C.lo.y + k22*C.hi.x;
        float s1 = k00*A.lo.y + k01*A.hi.x + k02*A.hi.y
                 + k10*B.lo.y + k11*B.hi.x + k12*B.hi.y
                 + k20*C.lo.y + k21*C.hi.x + k22*C.hi.y;
        float u0 = k00*B.lo.x + k01*B.lo.y + k02*B.hi.x
                 + k10*C.lo.x + k11*C.lo.y + k12*C.hi.x
                 + k20*D.lo.x + k21*D.lo.y + k22*D.hi.x;
        float u1 = k00*B.lo.y + k01*B.hi.x + k02*B.hi.y
                 + k10*C.lo.y + k11*C.hi.x + k12*C.hi.y
                 + k20*D.lo.y + k21*D.hi.x + k22*D.hi.y;

        if (valid) {
            // x0 even, OW even -> 8B-aligned float2 streaming stores;
            // output lines are never re-read, so evict-first is free L2 space
            __stcs((float2*)(po),      make_float2(s0, s1));
            __stcs((float2*)(po + OW), make_float2(u0, u1));
        }
        po += 2 * OW;

        A = C;
        B = D;
    }
}

extern "C" void kernel_launch(void* const* d_in, const int* in_sizes, int n_in,
                              void* d_out, int out_size)
{
    const float* inp = (const float*)d_in[0];   // (64,512,512,1) fp32
    const float* k   = (const float*)d_in[1];   // (3,3,1,1) fp32
    float* out = (float*)d_out;                 // (64,510,510,1) fp32

    // Closed-form LIF coefficient (double precision, host, once per capture).
    const double DT = 0.01, R = 3000.0, C = 10.0, NS = 1000.0;
    double v  = (R * 1.0) / (R * C) * DT;   // v0 = 1e-3
    double vt = v;
    for (int i = 0; i < 999; i++) {
        v  = v + (-v + R * 1.0) / (R * C) * DT;
        vt = (v + vt) / NS;
    }
    const float cscale = (float)vt;         // ~1.0008e-3

    dim3 block(TW);
    dim3 grid((510 + ROWS - 1) / ROWS, 64); // 16 x 64 = 1024 blocks, single wave
    snn_conv_kernel<<<grid, block>>>(inp, k, out, cscale);
}